// round 6
// baseline (speedup 1.0000x reference)
#include <cuda_runtime.h>
#include <cuda_bf16.h>
#include <math.h>
#include <cstdint>

#define B_   8
#define T_   1024
#define E_   1024
#define H_   16
#define D_   64
#define BH_  (B_*H_)   /* 128 */
#define M_   (B_*T_)   /* 8192 */

// ---------------- device scratch (no allocations allowed) ----------------
// packed split buffers: z-th slice for z in {q,k,v}; slot 0 reused for C later
__device__ __align__(256) __nv_bfloat16 g_Xhi3[(size_t)3 * M_ * E_];
__device__ __align__(256) __nv_bfloat16 g_Xlo3[(size_t)3 * M_ * E_];
__device__ __align__(256) __nv_bfloat16 g_Whi3[(size_t)3 * E_ * E_];
__device__ __align__(256) __nv_bfloat16 g_Wlo3[(size_t)3 * E_ * E_];

// attention bf16 operands (post-xpos), head-split
__device__ __align__(256) __nv_bfloat16 g_Qhi[(size_t)BH_ * T_ * D_];
__device__ __align__(256) __nv_bfloat16 g_Qlo[(size_t)BH_ * T_ * D_];
__device__ __align__(256) __nv_bfloat16 g_Khi[(size_t)BH_ * T_ * D_];
__device__ __align__(256) __nv_bfloat16 g_Klo[(size_t)BH_ * T_ * D_];
__device__ __align__(256) __nv_bfloat16 g_Vthi[(size_t)BH_ * D_ * T_];  // [bh, d, s]
__device__ __align__(256) __nv_bfloat16 g_Vtlo[(size_t)BH_ * D_ * T_];

// ================= PTX helpers =================
__device__ __forceinline__ uint32_t smem_u32(const void* p) {
    uint32_t a;
    asm("{ .reg .u64 t; cvta.to.shared.u64 t, %1; cvt.u32.u64 %0, t; }" : "=r"(a) : "l"(p));
    return a;
}
__device__ __forceinline__ void ldsm_x4(uint32_t& r0, uint32_t& r1, uint32_t& r2, uint32_t& r3,
                                        uint32_t addr) {
    asm volatile("ldmatrix.sync.aligned.m8n8.x4.shared.b16 {%0,%1,%2,%3}, [%4];"
                 : "=r"(r0), "=r"(r1), "=r"(r2), "=r"(r3) : "r"(addr));
}
__device__ __forceinline__ void mma_bf16(float* d, const uint32_t* a, const uint32_t* b) {
    asm volatile(
        "mma.sync.aligned.m16n8k16.row.col.f32.bf16.bf16.f32 "
        "{%0,%1,%2,%3}, {%4,%5,%6,%7}, {%8,%9}, {%0,%1,%2,%3};"
        : "+f"(d[0]), "+f"(d[1]), "+f"(d[2]), "+f"(d[3])
        : "r"(a[0]), "r"(a[1]), "r"(a[2]), "r"(a[3]), "r"(b[0]), "r"(b[1]));
}
#define CP_ASYNC16(dst, src) \
    asm volatile("cp.async.cg.shared.global [%0], [%1], 16;" :: "r"(dst), "l"(src))
#define CP_COMMIT() asm volatile("cp.async.commit_group;" ::: "memory")
#define CP_WAIT0()  asm volatile("cp.async.wait_group 0;" ::: "memory")
#define CP_WAIT1()  asm volatile("cp.async.wait_group 1;" ::: "memory")

__device__ __forceinline__ uint32_t pack_bf16(float x, float y) {
    __nv_bfloat162 t = __float22bfloat162_rn(make_float2(x, y));
    return *reinterpret_cast<uint32_t*>(&t);
}
__device__ __forceinline__ uint32_t pack_bf16_lo(float x, float y, uint32_t hi) {
    __nv_bfloat162 h = *reinterpret_cast<__nv_bfloat162*>(&hi);
    __nv_bfloat162 t = __float22bfloat162_rn(
        make_float2(x - __bfloat162float(h.x), y - __bfloat162float(h.y)));
    return *reinterpret_cast<uint32_t*>(&t);
}

// ================= fp32 -> bf16 hi/lo split kernels =================
__global__ __launch_bounds__(256) void split_kernel(
    const float* __restrict__ x, __nv_bfloat16* __restrict__ hi,
    __nv_bfloat16* __restrict__ lo, int n8)
{
    int idx = blockIdx.x * blockDim.x + threadIdx.x;
    if (idx >= n8) return;
    float4 v0 = *reinterpret_cast<const float4*>(x + (size_t)idx * 8);
    float4 v1 = *reinterpret_cast<const float4*>(x + (size_t)idx * 8 + 4);
    float v[8] = {v0.x, v0.y, v0.z, v0.w, v1.x, v1.y, v1.z, v1.w};
    __nv_bfloat16 hs[8], ls[8];
    #pragma unroll
    for (int i = 0; i < 8; i++) {
        hs[i] = __float2bfloat16(v[i]);
        ls[i] = __float2bfloat16(v[i] - __bfloat162float(hs[i]));
    }
    *reinterpret_cast<uint4*>(hi + (size_t)idx * 8) = *reinterpret_cast<uint4*>(hs);
    *reinterpret_cast<uint4*>(lo + (size_t)idx * 8) = *reinterpret_cast<uint4*>(ls);
}

// z-indexed triple split (activations q,k,v / weights wq,wk,wv)
__global__ __launch_bounds__(256) void split3_kernel(
    const float* __restrict__ x0, const float* __restrict__ x1, const float* __restrict__ x2,
    __nv_bfloat16* __restrict__ hi, __nv_bfloat16* __restrict__ lo, int n8)
{
    int idx = blockIdx.x * blockDim.x + threadIdx.x;
    if (idx >= n8) return;
    const int z = blockIdx.z;
    const float* x = (z == 0) ? x0 : (z == 1) ? x1 : x2;
    hi += (size_t)z * n8 * 8;
    lo += (size_t)z * n8 * 8;
    float4 v0 = *reinterpret_cast<const float4*>(x + (size_t)idx * 8);
    float4 v1 = *reinterpret_cast<const float4*>(x + (size_t)idx * 8 + 4);
    float v[8] = {v0.x, v0.y, v0.z, v0.w, v1.x, v1.y, v1.z, v1.w};
    __nv_bfloat16 hs[8], ls[8];
    #pragma unroll
    for (int i = 0; i < 8; i++) {
        hs[i] = __float2bfloat16(v[i]);
        ls[i] = __float2bfloat16(v[i] - __bfloat162float(hs[i]));
    }
    *reinterpret_cast<uint4*>(hi + (size_t)idx * 8) = *reinterpret_cast<uint4*>(hs);
    *reinterpret_cast<uint4*>(lo + (size_t)idx * 8) = *reinterpret_cast<uint4*>(ls);
}

// ================= 3-stage pipelined mma.sync GEMM mainloop =================
// 128 threads = 4 warps, CTA tile 128x128, warp tile 64x64, BK=32.
#define BKC      32
#define ROWB     80
#define TILE_B   (128 * ROWB)     /* 10240 B */
#define STAGE_B  (2 * TILE_B)
#define GEMM_SMEM (3 * STAGE_B)   /* 61440 B */
#define N_CHUNKS 96

__device__ __forceinline__ void gemm_mainloop(
    uint32_t sbase,
    const __nv_bfloat16* __restrict__ Xhi, const __nv_bfloat16* __restrict__ Xlo,
    const __nv_bfloat16* __restrict__ Whi, const __nv_bfloat16* __restrict__ Wlo,
    int m0, int n0, float acc[4][8][4])
{
    const int tid  = threadIdx.x;
    const int wid  = tid >> 5;
    const int lane = tid & 31;
    const int m_w = (wid & 1) * 64;
    const int n_w = (wid >> 1) * 64;

    // loader: 4 x 16B segs per tile per thread
    uint32_t l_soff[4];
    int l_grow[4], l_gcol[4];
    #pragma unroll
    for (int i = 0; i < 4; i++) {
        int idx = tid + i * 128;
        int row = idx >> 2, cs = idx & 3;
        l_soff[i] = (uint32_t)row * ROWB + cs * 16;
        l_grow[i] = row; l_gcol[i] = cs * 8;
    }

    #pragma unroll
    for (int i = 0; i < 4; i++)
        #pragma unroll
        for (int j = 0; j < 8; j++)
            #pragma unroll
            for (int q = 0; q < 4; q++) acc[i][j][q] = 0.f;

    const uint32_t a_base = (uint32_t)(m_w + (lane & 15)) * ROWB + (lane >> 4) * 16;
    const int bg = lane >> 3;
    const uint32_t b_rowoff = (uint32_t)(n_w + ((bg >> 1) * 8) + (lane & 7)) * ROWB;
    const uint32_t b_col = (uint32_t)(bg & 1) * 16;

    auto issue = [&](int c, int s) {
        const int p  = c >> 5;
        const int kc = (c & 31) * BKC;
        const __nv_bfloat16* sa = ((p == 2) ? Xlo : Xhi) + (size_t)m0 * E_ + kc;
        const __nv_bfloat16* sw = ((p == 1) ? Wlo : Whi) + (size_t)n0 * E_ + kc;
        const uint32_t ab = sbase + (uint32_t)s * STAGE_B;
        const uint32_t bb = ab + TILE_B;
        #pragma unroll
        for (int i = 0; i < 4; i++) {
            CP_ASYNC16(ab + l_soff[i], sa + (size_t)l_grow[i] * E_ + l_gcol[i]);
            CP_ASYNC16(bb + l_soff[i], sw + (size_t)l_grow[i] * E_ + l_gcol[i]);
        }
    };

    issue(0, 0); CP_COMMIT();
    issue(1, 1); CP_COMMIT();

    int s_cur = 0;
    for (int it = 0; it < N_CHUNKS; ++it) {
        CP_WAIT1();
        __syncthreads();

        int s_fill = s_cur + 2; if (s_fill >= 3) s_fill -= 3;
        if (it + 2 < N_CHUNKS) issue(it + 2, s_fill);
        CP_COMMIT();

        const uint32_t at = sbase + (uint32_t)s_cur * STAGE_B;
        const uint32_t bt = at + TILE_B;
        #pragma unroll
        for (int ks = 0; ks < 2; ks++) {
            uint32_t af[4][4];
            #pragma unroll
            for (int mf = 0; mf < 4; mf++)
                ldsm_x4(af[mf][0], af[mf][1], af[mf][2], af[mf][3],
                        at + a_base + (uint32_t)mf * 16 * ROWB + ks * 32);
            uint32_t bf[8][2];
            #pragma unroll
            for (int nf2 = 0; nf2 < 4; nf2++) {
                uint32_t r0, r1, r2, r3;
                ldsm_x4(r0, r1, r2, r3,
                        bt + b_rowoff + (uint32_t)nf2 * 16 * ROWB + b_col + ks * 32);
                bf[nf2 * 2 + 0][0] = r0; bf[nf2 * 2 + 0][1] = r1;
                bf[nf2 * 2 + 1][0] = r2; bf[nf2 * 2 + 1][1] = r3;
            }
            #pragma unroll
            for (int mf = 0; mf < 4; mf++)
                #pragma unroll
                for (int nf = 0; nf < 8; nf++)
                    mma_bf16(acc[mf][nf], af[mf], bf[nf]);
        }
        if (++s_cur >= 3) s_cur = 0;
    }
}

// ---------------- merged QKV projection with fused xpos/split epilogues ----------------
__global__ __launch_bounds__(128) void gemm_qkv(
    const float* __restrict__ bq, const float* __restrict__ bk, const float* __restrict__ bv)
{
    extern __shared__ char smem[];
    const uint32_t sbase = smem_u32(smem);
    const int z = blockIdx.z;
    const int m0 = blockIdx.y * 128;
    const int n0 = blockIdx.x * 128;
    const size_t xo = (size_t)z * M_ * E_;
    const size_t wo = (size_t)z * E_ * E_;
    const float* bias = (z == 0) ? bq : (z == 1) ? bk : bv;

    float acc[4][8][4];
    gemm_mainloop(sbase, g_Xhi3 + xo, g_Xlo3 + xo, g_Whi3 + wo, g_Wlo3 + wo,
                  m0, n0, acc);

    const int tid  = threadIdx.x;
    const int wid  = tid >> 5;
    const int lane = tid & 31;
    const int m_w = (wid & 1) * 64;
    const int n_w = (wid >> 1) * 64;
    const float alpha = (z == 0) ? 0.125f : 1.f;

    if (z < 2) {
        // Q/K: xpos rotary + hi/lo split, head-split layout [bh, t, d]
        __nv_bfloat16* Ohi = (z == 0) ? g_Qhi : g_Khi;
        __nv_bfloat16* Olo = (z == 0) ? g_Qlo : g_Klo;
        const float sgn = (z == 0) ? 1.f : -1.f;   // K uses 1/scale

        float lsj[8], ivf[8];
        #pragma unroll
        for (int nf = 0; nf < 8; nf++) {
            int n = n0 + n_w + nf * 8 + (lane & 3) * 2;
            int j = (n & 63) >> 1;
            float sj = (2.f * j + 25.6f) / 89.6f;
            lsj[nf] = log2f(sj) * (sgn / 1024.f);
            ivf[nf] = exp2f(-(float)j * (13.287712379549449f / 32.f));
        }

        #pragma unroll
        for (int mf = 0; mf < 4; mf++) {
            #pragma unroll
            for (int half = 0; half < 2; half++) {
                const int m = m0 + m_w + mf * 16 + (lane >> 2) + half * 8;
                const int bb = m >> 10;
                const int t  = m & 1023;
                const float pos = (float)(t - 512);
                #pragma unroll
                for (int nf = 0; nf < 8; nf++) {
                    const int n = n0 + n_w + nf * 8 + (lane & 3) * 2;
                    const int h = n >> 6, d = n & 63;
                    float y1 = (acc[mf][nf][half * 2 + 0] + __ldg(bias + n)) * alpha;
                    float y2 = (acc[mf][nf][half * 2 + 1] + __ldg(bias + n + 1)) * alpha;
                    float sc = exp2f(lsj[nf] * pos);
                    float sn, cs;
                    sincosf((float)t * ivf[nf], &sn, &cs);
                    cs *= sc; sn *= sc;
                    float o1 = y1 * cs - y2 * sn;
                    float o2 = y2 * cs + y1 * sn;
                    uint32_t hi = pack_bf16(o1, o2);
                    uint32_t lo = pack_bf16_lo(o1, o2, hi);
                    size_t ob = (((size_t)(bb * H_ + h)) * T_ + t) * D_ + d;
                    *reinterpret_cast<uint32_t*>(Ohi + ob) = hi;
                    *reinterpret_cast<uint32_t*>(Olo + ob) = lo;
                }
            }
        }
    } else {
        // V: transpose via smem to [bh, d, s] + hi/lo split
        float* tr = reinterpret_cast<float*>(smem);   // [64][132]
        __syncthreads();
        #pragma unroll
        for (int half_n = 0; half_n < 2; half_n++) {
            if ((wid >> 1) == half_n) {
                #pragma unroll
                for (int mf = 0; mf < 4; mf++)
                    #pragma unroll
                    for (int half = 0; half < 2; half++) {
                        const int m_local = m_w + mf * 16 + (lane >> 2) + half * 8;
                        #pragma unroll
                        for (int nf = 0; nf < 8; nf++) {
                            const int dd = nf * 8 + (lane & 3) * 2;
                            const int n = n0 + half_n * 64 + dd;
                            tr[dd * 132 + m_local] =
                                acc[mf][nf][half * 2 + 0] + __ldg(bias + n);
                            tr[(dd + 1) * 132 + m_local] =
                                acc[mf][nf][half * 2 + 1] + __ldg(bias + n + 1);
                        }
                    }
            }
            __syncthreads();
            {
                const int d = tid >> 1;
                const int tpart = (tid & 1) * 64;
                const int h = (n0 >> 6) + half_n;
                const int bh = (m0 >> 10) * H_ + h;
                const size_t ob = ((size_t)bh * D_ + d) * T_ + (m0 & 1023) + tpart;
                const float* row = tr + d * 132 + tpart;
                #pragma unroll
                for (int k = 0; k < 64; k += 2) {
                    float f1 = row[k], f2 = row[k + 1];
                    uint32_t hi = pack_bf16(f1, f2);
                    uint32_t lo = pack_bf16_lo(f1, f2, hi);
                    *reinterpret_cast<uint32_t*>(g_Vthi + ob + k) = hi;
                    *reinterpret_cast<uint32_t*>(g_Vtlo + ob + k) = lo;
                }
            }
            __syncthreads();
        }
    }
}

// ---------------- output projection ----------------
__global__ __launch_bounds__(128) void gemm_out(
    const float* __restrict__ bias, float* __restrict__ out)
{
    extern __shared__ char smem[];
    const uint32_t sbase = smem_u32(smem);
    const int m0 = blockIdx.y * 128;
    const int n0 = blockIdx.x * 128;

    float acc[4][8][4];
    gemm_mainloop(sbase, g_Xhi3, g_Xlo3, g_Whi3, g_Wlo3, m0, n0, acc);

    const int tid  = threadIdx.x;
    const int wid  = tid >> 5;
    const int lane = tid & 31;
    const int m_w = (wid & 1) * 64;
    const int n_w = (wid >> 1) * 64;

    #pragma unroll
    for (int mf = 0; mf < 4; mf++) {
        #pragma unroll
        for (int half = 0; half < 2; half++) {
            const int m = m0 + m_w + mf * 16 + (lane >> 2) + half * 8;
            #pragma unroll
            for (int nf = 0; nf < 8; nf++) {
                const int n = n0 + n_w + nf * 8 + (lane & 3) * 2;
                float2 v;
                v.x = acc[mf][nf][half * 2 + 0] + __ldg(bias + n);
                v.y = acc[mf][nf][half * 2 + 1] + __ldg(bias + n + 1);
                *reinterpret_cast<float2*>(out + (size_t)m * E_ + n) = v;
            }
        }
    }
}

// ================= Flash attention on mma.sync, double-buffered KV =================
#define ASM_Q    0
#define ASM_ST0  16384
#define ASM_STS  32768
#define ATTN_SMEM 81920

__global__ __launch_bounds__(128) void attn_mma()
{
    extern __shared__ char smem[];
    const uint32_t sb = smem_u32(smem);
    const int tid  = threadIdx.x;
    const int wid  = tid >> 5;
    const int lane = tid & 31;
    const int bh = blockIdx.x;
    const int qt = blockIdx.y;

    auto issue_kv = [&](int st, int s) {
        const int s0 = st * 64;
        const uint32_t base = sb + ASM_ST0 + (uint32_t)s * ASM_STS;
        const __nv_bfloat16* kh = g_Khi + ((size_t)bh * T_ + s0) * D_;
        const __nv_bfloat16* kl = g_Klo + ((size_t)bh * T_ + s0) * D_;
        const __nv_bfloat16* vh = g_Vthi + (size_t)bh * D_ * T_ + s0;
        const __nv_bfloat16* vl = g_Vtlo + (size_t)bh * D_ * T_ + s0;
        #pragma unroll
        for (int i = 0; i < 4; i++) {
            int idx = tid + i * 128;
            int row = idx >> 3, seg = idx & 7;
            uint32_t off = (uint32_t)row * 128 + ((seg ^ (row & 7)) * 16);
            CP_ASYNC16(base + off,         kh + (size_t)row * D_ + seg * 8);
            CP_ASYNC16(base + 8192 + off,  kl + (size_t)row * D_ + seg * 8);
            CP_ASYNC16(base + 16384 + off, vh + (size_t)row * T_ + seg * 8);
            CP_ASYNC16(base + 24576 + off, vl + (size_t)row * T_ + seg * 8);
        }
    };

    {
        const __nv_bfloat16* qh = g_Qhi + ((size_t)bh * T_ + qt * 64) * D_;
        const __nv_bfloat16* ql = g_Qlo + ((size_t)bh * T_ + qt * 64) * D_;
        #pragma unroll
        for (int i = 0; i < 4; i++) {
            int idx = tid + i * 128;
            int row = idx >> 3, seg = idx & 7;
            uint32_t off = (uint32_t)row * 128 + ((seg ^ (row & 7)) * 16);
            CP_ASYNC16(sb + ASM_Q + off,        qh + (size_t)row * D_ + seg * 8);
            CP_ASYNC16(sb + ASM_Q + 8192 + off, ql + (size_t)row * D_ + seg * 8);
        }
        issue_kv(0, 0);
        CP_COMMIT(); CP_WAIT0();
        __syncthreads();
    }

    uint32_t qh[4][4], ql[4][4];
    {
        const int row = wid * 16 + (lane & 15);
        const uint32_t rb = (uint32_t)row * 128;
        #pragma unroll
        for (int ks = 0; ks < 4; ks++) {
            int seg = ks * 2 + (lane >> 4);
            uint32_t off = rb + ((seg ^ (row & 7)) * 16);
            ldsm_x4(qh[ks][0], qh[ks][1], qh[ks][2], qh[ks][3], sb + ASM_Q + off);
            ldsm_x4(ql[ks][0], ql[ks][1], ql[ks][2], ql[ks][3], sb + ASM_Q + 8192 + off);
        }
    }

    float m0 = -1e30f, m1 = -1e30f, l0 = 0.f, l1 = 0.f;
    float o[8][4];
    #pragma unroll
    for (int nf = 0; nf < 8; nf++)
        #pragma unroll
        for (int q = 0; q < 4; q++) o[nf][q] = 0.f;

    const int bg = lane >> 3;
    const int brow_lo = ((bg >> 1) * 8) + (lane & 7);
    const int bseg0 = bg & 1;

    for (int st = 0; st < 16; st++) {
        const int buf = st & 1;
        if (st + 1 < 16) issue_kv(st + 1, buf ^ 1);
        CP_COMMIT();

        const uint32_t kbase = sb + ASM_ST0 + (uint32_t)buf * ASM_STS;
        const uint32_t vbase = kbase + 16384;

        float sacc[8][4];
        #pragma unroll
        for (int nf = 0; nf < 8; nf++)
            #pragma unroll
            for (int q = 0; q < 4; q++) sacc[nf][q] = 0.f;

        #pragma unroll
        for (int ph = 0; ph < 3; ph++) {
            const uint32_t (*aq)[4] = (ph == 2) ? ql : qh;
            const uint32_t kt = kbase + ((ph == 1) ? 8192 : 0);
            #pragma unroll
            for (int ks = 0; ks < 4; ks++) {
                uint32_t bf[8][2];
                #pragma unroll
                for (int nf2 = 0; nf2 < 4; nf2++) {
                    int row = nf2 * 16 + brow_lo;
                    int seg = (ks * 2 + bseg0) ^ (row & 7);
                    uint32_t r0, r1, r2, r3;
                    ldsm_x4(r0, r1, r2, r3, kt + (uint32_t)row * 128 + seg * 16);
                    bf[nf2 * 2 + 0][0] = r0; bf[nf2 * 2 + 0][1] = r1;
                    bf[nf2 * 2 + 1][0] = r2; bf[nf2 * 2 + 1][1] = r3;
                }
                #pragma unroll
                for (int nf = 0; nf < 8; nf++)
                    mma_bf16(sacc[nf], aq[ks], bf[nf]);
            }
        }

        float mx0 = m0, mx1 = m1;
        #pragma unroll
        for (int nf = 0; nf < 8; nf++) {
            mx0 = fmaxf(mx0, fmaxf(sacc[nf][0], sacc[nf][1]));
            mx1 = fmaxf(mx1, fmaxf(sacc[nf][2], sacc[nf][3]));
        }
        mx0 = fmaxf(mx0, __shfl_xor_sync(0xffffffffu, mx0, 1));
        mx0 = fmaxf(mx0, __shfl_xor_sync(0xffffffffu, mx0, 2));
        mx1 = fmaxf(mx1, __shfl_xor_sync(0xffffffffu, mx1, 1));
        mx1 = fmaxf(mx1, __shfl_xor_sync(0xffffffffu, mx1, 2));

        const float c0 = __expf(m0 - mx0);
        const float c1 = __expf(m1 - mx1);
        m0 = mx0; m1 = mx1;
        l0 *= c0; l1 *= c1;
        #pragma unroll
        for (int nf = 0; nf < 8; nf++) {
            o[nf][0] *= c0; o[nf][1] *= c0;
            o[nf][2] *= c1; o[nf][3] *= c1;
        }
        #pragma unroll
        for (int nf = 0; nf < 8; nf++) {
            float e0 = __expf(sacc[nf][0] - m0);
            float e1 = __expf(sacc[nf][1] - m0);
            float e2 = __expf(sacc[nf][2] - m1);
            float e3 = __expf(sacc[nf][3] - m1);
            l0 += e0 + e1; l1 += e2 + e3;
            sacc[nf][0] = e0; sacc[nf][1] = e1;
            sacc[nf][2] = e2; sacc[nf][3] = e3;
        }

        uint32_t phi[4][4], plo[4][4];
        #pragma unroll
        for (int ks = 0; ks < 4; ks++) {
            phi[ks][0] = pack_bf16(sacc[2 * ks][0],     sacc[2 * ks][1]);
            phi[ks][1] = pack_bf16(sacc[2 * ks][2],     sacc[2 * ks][3]);
            phi[ks][2] = pack_bf16(sacc[2 * ks + 1][0], sacc[2 * ks + 1][1]);
            phi[ks][3] = pack_bf16(sacc[2 * ks + 1][2], sacc[2 * ks + 1][3]);
            plo[ks][0] = pack_bf16_lo(sacc[2 * ks][0],     sacc[2 * ks][1],     phi[ks][0]);
            plo[ks][1] = pack_bf16_lo(sacc[2 * ks][2],     sacc[2 * ks][3],     phi[ks][1]);
            plo[ks][2] = pack_bf16_lo(sacc[2 * ks + 1][0], sacc[2 * ks + 1][1], phi[ks][2]);
            plo[ks][3] = pack_bf16_lo(sacc[2 * ks + 1][2], sacc[2 * ks + 1][3], phi[ks][3]);
        }

        #pragma unroll
        for (int ph = 0; ph < 3; ph++) {
            const uint32_t (*ap)[4] = (ph == 2) ? plo : phi;
            const uint32_t vt = vbase + ((ph == 1) ? 8192 : 0);
            #pragma unroll
            for (int ks = 0; ks < 4; ks++) {
                uint32_t bf[8][2];
                #pragma unroll
                for (int nf2 = 0; nf2 < 4; nf2++) {
                    int row = nf2 * 16 + brow_lo;
                    int seg = (ks * 2 + bseg0) ^ (row & 7);
                    uint32_t r0, r1, r2, r3;
                    ldsm_x4(r0, r1, r2, r3, vt + (uint32_t)row * 128 + seg * 16);
                    bf[nf2 * 2 + 0][0] = r0; bf[nf2 * 2 + 0][1] = r1;
                    bf[nf2 * 2 + 1][0] = r2; bf[nf2 * 2 + 1][1] = r3;
                }
                #pragma unroll
                for (int nf = 0; nf < 8; nf++)
                    mma_bf16(o[nf], ap[ks], bf[nf]);
            }
        }

        CP_WAIT0();
        __syncthreads();
    }

    // ---- finalize: write C directly as bf16 hi/lo (fused split) ----
    l0 += __shfl_xor_sync(0xffffffffu, l0, 1);
    l0 += __shfl_xor_sync(0xffffffffu, l0, 2);
    l1 += __shfl_xor_sync(0xffffffffu, l1, 1);
    l1 += __shfl_xor_sync(0xffffffffu, l1, 2);
    const float inv0 = 1.f / l0;
    const float inv1 = 1.f / l1;

    const int t0 = qt * 64 + wid * 16 + (lane >> 2);
    const int b = bh >> 4, h = bh & 15;
    const size_t c0i = ((size_t)(b * T_ + t0)) * E_ + h * D_ + (lane & 3) * 2;
    const size_t c1i = c0i + (size_t)8 * E_;
    #pragma unroll
    for (int nf = 0; nf < 8; nf++) {
        float a0 = o[nf][0] * inv0, a1 = o[nf][1] * inv0;
        float b0 = o[nf][2] * inv1, b1 = o[nf][3] * inv1;
        uint32_t h0 = pack_bf16(a0, a1), h1 = pack_bf16(b0, b1);
        uint32_t l0w = pack_bf16_lo(a0, a1, h0), l1w = pack_bf16_lo(b0, b1, h1);
        *reinterpret_cast<uint32_t*>(g_Xhi3 + c0i + nf * 8) = h0;
        *reinterpret_cast<uint32_t*>(g_Xlo3 + c0i + nf * 8) = l0w;
        *reinterpret_cast<uint32_t*>(g_Xhi3 + c1i + nf * 8) = h1;
        *reinterpret_cast<uint32_t*>(g_Xlo3 + c1i + nf * 8) = l1w;
    }
}

// ---------------- launch ----------------
extern "C" void kernel_launch(void* const* d_in, const int* in_sizes, int n_in,
                              void* d_out, int out_size)
{
    const float* query = (const float*)d_in[0];
    const float* key   = (const float*)d_in[1];
    const float* value = (const float*)d_in[2];
    const float* wq    = (const float*)d_in[3];
    const float* bq    = (const float*)d_in[4];
    const float* wk    = (const float*)d_in[5];
    const float* bk    = (const float*)d_in[6];
    const float* wv    = (const float*)d_in[7];
    const float* bv    = (const float*)d_in[8];
    const float* wo    = (const float*)d_in[9];
    const float* bo    = (const float*)d_in[10];
    float* out = (float*)d_out;

    __nv_bfloat16 *Xhi3, *Xlo3, *Whi3, *Wlo3;
    cudaGetSymbolAddress((void**)&Xhi3, g_Xhi3);
    cudaGetSymbolAddress((void**)&Xlo3, g_Xlo3);
    cudaGetSymbolAddress((void**)&Whi3, g_Whi3);
    cudaGetSymbolAddress((void**)&Wlo3, g_Wlo3);

    static bool attr_done = false;
    if (!attr_done) {
        cudaFuncSetAttribute(gemm_qkv, cudaFuncAttributeMaxDynamicSharedMemorySize, GEMM_SMEM);
        cudaFuncSetAttribute(gemm_out, cudaFuncAttributeMaxDynamicSharedMemorySize, GEMM_SMEM);
        cudaFuncSetAttribute(attn_mma, cudaFuncAttributeMaxDynamicSharedMemorySize, ATTN_SMEM);
        attr_done = true;
    }

    const int actn8 = (M_ * E_) / 8;   // 1,048,576
    const int wn8   = (E_ * E_) / 8;   // 131,072

    split3_kernel<<<dim3(actn8 / 256, 1, 3), 256>>>(query, key, value, Xhi3, Xlo3, actn8);
    split3_kernel<<<dim3(wn8 / 256, 1, 3), 256>>>(wq, wk, wv, Whi3, Wlo3, wn8);

    gemm_qkv<<<dim3(E_ / 128, M_ / 128, 3), 128, GEMM_SMEM>>>(bq, bk, bv);

    // wo split can overlap conceptually; launch before attention
    split_kernel<<<wn8 / 256, 256>>>(wo, Whi3, Wlo3, wn8);

    attn_mma<<<dim3(BH_, T_ / 64), 128, ATTN_SMEM>>>();   // writes Chi/Clo into Xhi3/Xlo3

    gemm_out<<<dim3(E_ / 128, M_ / 128), 128, GEMM_SMEM>>>(bo, out);
}

// round 7
// speedup vs baseline: 2.7279x; 2.7279x over previous
#include <cuda_runtime.h>
#include <cuda_fp16.h>
#include <math.h>
#include <cstdint>

#define B_   8
#define T_   1024
#define E_   1024
#define H_   16
#define D_   64
#define BH_  (B_*H_)   /* 128 */
#define M_   (B_*T_)   /* 8192 */

// ---------------- device scratch (no allocations allowed) ----------------
// fp16 operand buffers; slot 0 of g_X3 is reused for attention output C
__device__ __align__(256) __half g_X3[(size_t)3 * M_ * E_];
__device__ __align__(256) __half g_W3[(size_t)3 * E_ * E_];
__device__ __align__(256) __half g_Qh[(size_t)BH_ * T_ * D_];   // post-xpos, [bh,t,d]
__device__ __align__(256) __half g_Kh[(size_t)BH_ * T_ * D_];
__device__ __align__(256) __half g_Vt[(size_t)BH_ * D_ * T_];   // [bh,d,s]

// ================= PTX helpers =================
__device__ __forceinline__ uint32_t smem_u32(const void* p) {
    uint32_t a;
    asm("{ .reg .u64 t; cvta.to.shared.u64 t, %1; cvt.u32.u64 %0, t; }" : "=r"(a) : "l"(p));
    return a;
}
__device__ __forceinline__ void ldsm_x4(uint32_t& r0, uint32_t& r1, uint32_t& r2, uint32_t& r3,
                                        uint32_t addr) {
    asm volatile("ldmatrix.sync.aligned.m8n8.x4.shared.b16 {%0,%1,%2,%3}, [%4];"
                 : "=r"(r0), "=r"(r1), "=r"(r2), "=r"(r3) : "r"(addr));
}
__device__ __forceinline__ void mma_f16(float* d, const uint32_t* a, const uint32_t* b) {
    asm volatile(
        "mma.sync.aligned.m16n8k16.row.col.f32.f16.f16.f32 "
        "{%0,%1,%2,%3}, {%4,%5,%6,%7}, {%8,%9}, {%0,%1,%2,%3};"
        : "+f"(d[0]), "+f"(d[1]), "+f"(d[2]), "+f"(d[3])
        : "r"(a[0]), "r"(a[1]), "r"(a[2]), "r"(a[3]), "r"(b[0]), "r"(b[1]));
}
#define CP_ASYNC16(dst, src) \
    asm volatile("cp.async.cg.shared.global [%0], [%1], 16;" :: "r"(dst), "l"(src))
#define CP_COMMIT() asm volatile("cp.async.commit_group;" ::: "memory")
#define CP_WAIT0()  asm volatile("cp.async.wait_group 0;" ::: "memory")
#define CP_WAIT1()  asm volatile("cp.async.wait_group 1;" ::: "memory")

__device__ __forceinline__ uint32_t pack_h2(float x, float y) {
    __half2 t = __floats2half2_rn(x, y);
    return *reinterpret_cast<uint32_t*>(&t);
}

// ================= fp32 -> fp16 convert kernels =================
__global__ __launch_bounds__(256) void conv3_kernel(
    const float* __restrict__ x0, const float* __restrict__ x1, const float* __restrict__ x2,
    __half* __restrict__ y, int n8)
{
    int idx = blockIdx.x * blockDim.x + threadIdx.x;
    if (idx >= n8) return;
    const int z = blockIdx.z;
    const float* x = (z == 0) ? x0 : (z == 1) ? x1 : x2;
    y += (size_t)z * n8 * 8;
    float4 v0 = *reinterpret_cast<const float4*>(x + (size_t)idx * 8);
    float4 v1 = *reinterpret_cast<const float4*>(x + (size_t)idx * 8 + 4);
    __half h[8];
    h[0] = __float2half_rn(v0.x); h[1] = __float2half_rn(v0.y);
    h[2] = __float2half_rn(v0.z); h[3] = __float2half_rn(v0.w);
    h[4] = __float2half_rn(v1.x); h[5] = __float2half_rn(v1.y);
    h[6] = __float2half_rn(v1.z); h[7] = __float2half_rn(v1.w);
    *reinterpret_cast<uint4*>(y + (size_t)idx * 8) = *reinterpret_cast<uint4*>(h);
}

__global__ __launch_bounds__(256) void conv1_kernel(
    const float* __restrict__ x, __half* __restrict__ y, int n8)
{
    int idx = blockIdx.x * blockDim.x + threadIdx.x;
    if (idx >= n8) return;
    float4 v0 = *reinterpret_cast<const float4*>(x + (size_t)idx * 8);
    float4 v1 = *reinterpret_cast<const float4*>(x + (size_t)idx * 8 + 4);
    __half h[8];
    h[0] = __float2half_rn(v0.x); h[1] = __float2half_rn(v0.y);
    h[2] = __float2half_rn(v0.z); h[3] = __float2half_rn(v0.w);
    h[4] = __float2half_rn(v1.x); h[5] = __float2half_rn(v1.y);
    h[6] = __float2half_rn(v1.z); h[7] = __float2half_rn(v1.w);
    *reinterpret_cast<uint4*>(y + (size_t)idx * 8) = *reinterpret_cast<uint4*>(h);
}

// ================= 3-stage pipelined fp16 mma.sync GEMM mainloop =================
// 256 threads = 8 warps, CTA tile 128x128, warp tile 64x32, BK=32, K=1024.
#define BKC      32
#define ROWB     80                 /* 32 fp16 (64B) + 16B pad */
#define TILE_B   (128 * ROWB)       /* 10240 B */
#define STAGE_B  (2 * TILE_B)
#define GEMM_SMEM (3 * STAGE_B)     /* 61440 B */
#define N_CHUNKS 32

__device__ __forceinline__ void gemm_mainloop(
    uint32_t sbase, const __half* __restrict__ X, const __half* __restrict__ W,
    int m0, int n0, float acc[4][4][4])
{
    const int tid  = threadIdx.x;
    const int wid  = tid >> 5;
    const int lane = tid & 31;
    const int m_w = (wid & 1) * 64;
    const int n_w = (wid >> 1) * 32;

    uint32_t l_soff[2];
    int l_grow[2], l_gcol[2];
    #pragma unroll
    for (int i = 0; i < 2; i++) {
        int idx = tid + i * 256;
        int row = idx >> 2, cs = idx & 3;
        l_soff[i] = (uint32_t)row * ROWB + cs * 16;
        l_grow[i] = row; l_gcol[i] = cs * 8;
    }

    #pragma unroll
    for (int i = 0; i < 4; i++)
        #pragma unroll
        for (int j = 0; j < 4; j++)
            #pragma unroll
            for (int q = 0; q < 4; q++) acc[i][j][q] = 0.f;

    const uint32_t a_base = (uint32_t)(m_w + (lane & 15)) * ROWB + (lane >> 4) * 16;
    const int bg = lane >> 3;
    const uint32_t b_rowoff = (uint32_t)(n_w + ((bg >> 1) * 8) + (lane & 7)) * ROWB;
    const uint32_t b_col = (uint32_t)(bg & 1) * 16;

    auto issue = [&](int c, int s) {
        const __half* sa = X + (size_t)m0 * E_ + c * BKC;
        const __half* sw = W + (size_t)n0 * E_ + c * BKC;
        const uint32_t ab = sbase + (uint32_t)s * STAGE_B;
        const uint32_t bb = ab + TILE_B;
        #pragma unroll
        for (int i = 0; i < 2; i++) {
            CP_ASYNC16(ab + l_soff[i], sa + (size_t)l_grow[i] * E_ + l_gcol[i]);
            CP_ASYNC16(bb + l_soff[i], sw + (size_t)l_grow[i] * E_ + l_gcol[i]);
        }
    };

    issue(0, 0); CP_COMMIT();
    issue(1, 1); CP_COMMIT();

    int s_cur = 0;
    for (int it = 0; it < N_CHUNKS; ++it) {
        CP_WAIT1();
        __syncthreads();

        int s_fill = s_cur + 2; if (s_fill >= 3) s_fill -= 3;
        if (it + 2 < N_CHUNKS) issue(it + 2, s_fill);
        CP_COMMIT();

        const uint32_t at = sbase + (uint32_t)s_cur * STAGE_B;
        const uint32_t bt = at + TILE_B;
        #pragma unroll
        for (int ks = 0; ks < 2; ks++) {
            uint32_t af[4][4];
            #pragma unroll
            for (int mf = 0; mf < 4; mf++)
                ldsm_x4(af[mf][0], af[mf][1], af[mf][2], af[mf][3],
                        at + a_base + (uint32_t)mf * 16 * ROWB + ks * 32);
            uint32_t bf[4][2];
            #pragma unroll
            for (int nf2 = 0; nf2 < 2; nf2++) {
                uint32_t r0, r1, r2, r3;
                ldsm_x4(r0, r1, r2, r3,
                        bt + b_rowoff + (uint32_t)nf2 * 16 * ROWB + b_col + ks * 32);
                bf[nf2 * 2 + 0][0] = r0; bf[nf2 * 2 + 0][1] = r1;
                bf[nf2 * 2 + 1][0] = r2; bf[nf2 * 2 + 1][1] = r3;
            }
            #pragma unroll
            for (int mf = 0; mf < 4; mf++)
                #pragma unroll
                for (int nf = 0; nf < 4; nf++)
                    mma_f16(acc[mf][nf], af[mf], bf[nf]);
        }
        if (++s_cur >= 3) s_cur = 0;
    }
}

// ---------------- merged QKV projection with fused xpos / transpose epilogues ----------------
__global__ __launch_bounds__(256, 2) void gemm_qkv(
    const float* __restrict__ bq, const float* __restrict__ bk, const float* __restrict__ bv)
{
    extern __shared__ char smem[];
    const uint32_t sbase = smem_u32(smem);
    const int z = blockIdx.z;
    const int m0 = blockIdx.y * 128;
    const int n0 = blockIdx.x * 128;
    const float* bias = (z == 0) ? bq : (z == 1) ? bk : bv;

    float acc[4][4][4];
    gemm_mainloop(sbase, g_X3 + (size_t)z * M_ * E_, g_W3 + (size_t)z * E_ * E_,
                  m0, n0, acc);

    const int tid  = threadIdx.x;
    const int wid  = tid >> 5;
    const int lane = tid & 31;
    const int m_w = (wid & 1) * 64;
    const int n_w = (wid >> 1) * 32;

    if (z < 2) {
        // Q/K: xpos rotary + fp16 pack, head-split layout [bh, t, d]
        __half* O = (z == 0) ? g_Qh : g_Kh;
        const float alpha = (z == 0) ? 0.125f : 1.f;
        const float sgn = (z == 0) ? 1.f : -1.f;   // K uses 1/scale

        float lsj[4], ivf[4];
        #pragma unroll
        for (int nf = 0; nf < 4; nf++) {
            int n = n0 + n_w + nf * 8 + (lane & 3) * 2;
            int j = (n & 63) >> 1;
            float sj = (2.f * j + 25.6f) / 89.6f;
            lsj[nf] = log2f(sj) * (sgn / 1024.f);
            ivf[nf] = exp2f(-(float)j * (13.287712379549449f / 32.f));
        }

        #pragma unroll
        for (int mf = 0; mf < 4; mf++) {
            #pragma unroll
            for (int half = 0; half < 2; half++) {
                const int m = m0 + m_w + mf * 16 + (lane >> 2) + half * 8;
                const int bb = m >> 10;
                const int t  = m & 1023;
                const float pos = (float)(t - 512);
                #pragma unroll
                for (int nf = 0; nf < 4; nf++) {
                    const int n = n0 + n_w + nf * 8 + (lane & 3) * 2;
                    const int h = n >> 6, d = n & 63;
                    float y1 = (acc[mf][nf][half * 2 + 0] + __ldg(bias + n)) * alpha;
                    float y2 = (acc[mf][nf][half * 2 + 1] + __ldg(bias + n + 1)) * alpha;
                    float sc = exp2f(lsj[nf] * pos);
                    float sn, cs;
                    sincosf((float)t * ivf[nf], &sn, &cs);
                    cs *= sc; sn *= sc;
                    float o1 = y1 * cs - y2 * sn;
                    float o2 = y2 * cs + y1 * sn;
                    size_t ob = (((size_t)(bb * H_ + h)) * T_ + t) * D_ + d;
                    *reinterpret_cast<uint32_t*>(O + ob) = pack_h2(o1, o2);
                }
            }
        }
    } else {
        // V: transpose via smem to [bh, d, s] fp16
        float* tr = reinterpret_cast<float*>(smem);   // [64][132] floats = 33792 B
        __syncthreads();
        #pragma unroll
        for (int half_n = 0; half_n < 2; half_n++) {
            if (((wid >> 1) >> 1) == half_n) {
                #pragma unroll
                for (int mf = 0; mf < 4; mf++)
                    #pragma unroll
                    for (int half = 0; half < 2; half++) {
                        const int m_local = m_w + mf * 16 + (lane >> 2) + half * 8;
                        #pragma unroll
                        for (int nf = 0; nf < 4; nf++) {
                            const int dd = ((wid >> 1) & 1) * 32 + nf * 8 + (lane & 3) * 2;
                            const int n = n0 + half_n * 64 + dd;
                            tr[dd * 132 + m_local] =
                                acc[mf][nf][half * 2 + 0] + __ldg(bias + n);
                            tr[(dd + 1) * 132 + m_local] =
                                acc[mf][nf][half * 2 + 1] + __ldg(bias + n + 1);
                        }
                    }
            }
            __syncthreads();
            {
                const int d = tid >> 2;
                const int tpart = (tid & 3) * 32;
                const int h = (n0 >> 6) + half_n;
                const int bh = (m0 >> 10) * H_ + h;
                const size_t ob = ((size_t)bh * D_ + d) * T_ + (m0 & 1023) + tpart;
                const float* row = tr + d * 132 + tpart;
                #pragma unroll
                for (int k = 0; k < 32; k += 2) {
                    *reinterpret_cast<uint32_t*>(g_Vt + ob + k) =
                        pack_h2(row[k], row[k + 1]);
                }
            }
            __syncthreads();
        }
    }
}

// ---------------- output projection ----------------
__global__ __launch_bounds__(256, 2) void gemm_out(
    const float* __restrict__ bias, float* __restrict__ out)
{
    extern __shared__ char smem[];
    const uint32_t sbase = smem_u32(smem);
    const int m0 = blockIdx.y * 128;
    const int n0 = blockIdx.x * 128;

    float acc[4][4][4];
    gemm_mainloop(sbase, g_X3, g_W3, m0, n0, acc);

    const int tid  = threadIdx.x;
    const int wid  = tid >> 5;
    const int lane = tid & 31;
    const int m_w = (wid & 1) * 64;
    const int n_w = (wid >> 1) * 32;

    #pragma unroll
    for (int mf = 0; mf < 4; mf++) {
        #pragma unroll
        for (int half = 0; half < 2; half++) {
            const int m = m0 + m_w + mf * 16 + (lane >> 2) + half * 8;
            #pragma unroll
            for (int nf = 0; nf < 4; nf++) {
                const int n = n0 + n_w + nf * 8 + (lane & 3) * 2;
                float2 v;
                v.x = acc[mf][nf][half * 2 + 0] + __ldg(bias + n);
                v.y = acc[mf][nf][half * 2 + 1] + __ldg(bias + n + 1);
                *reinterpret_cast<float2*>(out + (size_t)m * E_ + n) = v;
            }
        }
    }
}

// ================= Flash attention, fp16 single-term, double-buffered KV =================
// smem: Q 8KB at 0; stage s at 8192 + s*16384: K +0, V +8192.  total 40960 B
#define ASM_ST0  8192
#define ASM_STS  16384
#define ATTN_SMEM 40960

__global__ __launch_bounds__(128) void attn_mma()
{
    extern __shared__ char smem[];
    const uint32_t sb = smem_u32(smem);
    const int tid  = threadIdx.x;
    const int wid  = tid >> 5;
    const int lane = tid & 31;
    const int bh = blockIdx.x;
    const int qt = blockIdx.y;

    auto issue_kv = [&](int st, int s) {
        const int s0 = st * 64;
        const uint32_t base = sb + ASM_ST0 + (uint32_t)s * ASM_STS;
        const __half* kh = g_Kh + ((size_t)bh * T_ + s0) * D_;
        const __half* vh = g_Vt + (size_t)bh * D_ * T_ + s0;
        #pragma unroll
        for (int i = 0; i < 4; i++) {
            int idx = tid + i * 128;
            int row = idx >> 3, seg = idx & 7;
            uint32_t off = (uint32_t)row * 128 + ((seg ^ (row & 7)) * 16);
            CP_ASYNC16(base + off,        kh + (size_t)row * D_ + seg * 8);
            CP_ASYNC16(base + 8192 + off, vh + (size_t)row * T_ + seg * 8);
        }
    };

    {
        const __half* qh = g_Qh + ((size_t)bh * T_ + qt * 64) * D_;
        #pragma unroll
        for (int i = 0; i < 4; i++) {
            int idx = tid + i * 128;
            int row = idx >> 3, seg = idx & 7;
            uint32_t off = (uint32_t)row * 128 + ((seg ^ (row & 7)) * 16);
            CP_ASYNC16(sb + off, qh + (size_t)row * D_ + seg * 8);
        }
        issue_kv(0, 0);
        CP_COMMIT(); CP_WAIT0();
        __syncthreads();
    }

    uint32_t qf[4][4];
    {
        const int row = wid * 16 + (lane & 15);
        const uint32_t rb = (uint32_t)row * 128;
        #pragma unroll
        for (int ks = 0; ks < 4; ks++) {
            int seg = ks * 2 + (lane >> 4);
            uint32_t off = rb + ((seg ^ (row & 7)) * 16);
            ldsm_x4(qf[ks][0], qf[ks][1], qf[ks][2], qf[ks][3], sb + off);
        }
    }

    float m0 = -1e30f, m1 = -1e30f, l0 = 0.f, l1 = 0.f;
    float o[8][4];
    #pragma unroll
    for (int nf = 0; nf < 8; nf++)
        #pragma unroll
        for (int q = 0; q < 4; q++) o[nf][q] = 0.f;

    const int bg = lane >> 3;
    const int brow_lo = ((bg >> 1) * 8) + (lane & 7);
    const int bseg0 = bg & 1;

    for (int st = 0; st < 16; st++) {
        const int buf = st & 1;
        if (st + 1 < 16) issue_kv(st + 1, buf ^ 1);
        CP_COMMIT();

        const uint32_t kbase = sb + ASM_ST0 + (uint32_t)buf * ASM_STS;
        const uint32_t vbase = kbase + 8192;

        // ---- S = Q K^T ----
        float sacc[8][4];
        #pragma unroll
        for (int nf = 0; nf < 8; nf++)
            #pragma unroll
            for (int q = 0; q < 4; q++) sacc[nf][q] = 0.f;

        #pragma unroll
        for (int ks = 0; ks < 4; ks++) {
            uint32_t bf[8][2];
            #pragma unroll
            for (int nf2 = 0; nf2 < 4; nf2++) {
                int row = nf2 * 16 + brow_lo;
                int seg = (ks * 2 + bseg0) ^ (row & 7);
                uint32_t r0, r1, r2, r3;
                ldsm_x4(r0, r1, r2, r3, kbase + (uint32_t)row * 128 + seg * 16);
                bf[nf2 * 2 + 0][0] = r0; bf[nf2 * 2 + 0][1] = r1;
                bf[nf2 * 2 + 1][0] = r2; bf[nf2 * 2 + 1][1] = r3;
            }
            #pragma unroll
            for (int nf = 0; nf < 8; nf++)
                mma_f16(sacc[nf], qf[ks], bf[nf]);
        }

        // ---- online softmax ----
        float mx0 = m0, mx1 = m1;
        #pragma unroll
        for (int nf = 0; nf < 8; nf++) {
            mx0 = fmaxf(mx0, fmaxf(sacc[nf][0], sacc[nf][1]));
            mx1 = fmaxf(mx1, fmaxf(sacc[nf][2], sacc[nf][3]));
        }
        mx0 = fmaxf(mx0, __shfl_xor_sync(0xffffffffu, mx0, 1));
        mx0 = fmaxf(mx0, __shfl_xor_sync(0xffffffffu, mx0, 2));
        mx1 = fmaxf(mx1, __shfl_xor_sync(0xffffffffu, mx1, 1));
        mx1 = fmaxf(mx1, __shfl_xor_sync(0xffffffffu, mx1, 2));

        const float c0 = __expf(m0 - mx0);
        const float c1 = __expf(m1 - mx1);
        m0 = mx0; m1 = mx1;
        l0 *= c0; l1 *= c1;
        #pragma unroll
        for (int nf = 0; nf < 8; nf++) {
            o[nf][0] *= c0; o[nf][1] *= c0;
            o[nf][2] *= c1; o[nf][3] *= c1;
        }
        #pragma unroll
        for (int nf = 0; nf < 8; nf++) {
            float e0 = __expf(sacc[nf][0] - m0);
            float e1 = __expf(sacc[nf][1] - m0);
            float e2 = __expf(sacc[nf][2] - m1);
            float e3 = __expf(sacc[nf][3] - m1);
            l0 += e0 + e1; l1 += e2 + e3;
            sacc[nf][0] = e0; sacc[nf][1] = e1;
            sacc[nf][2] = e2; sacc[nf][3] = e3;
        }

        // ---- P -> fp16 A-fragments ----
        uint32_t pf[4][4];
        #pragma unroll
        for (int ks = 0; ks < 4; ks++) {
            pf[ks][0] = pack_h2(sacc[2 * ks][0],     sacc[2 * ks][1]);
            pf[ks][1] = pack_h2(sacc[2 * ks][2],     sacc[2 * ks][3]);
            pf[ks][2] = pack_h2(sacc[2 * ks + 1][0], sacc[2 * ks + 1][1]);
            pf[ks][3] = pack_h2(sacc[2 * ks + 1][2], sacc[2 * ks + 1][3]);
        }

        // ---- O += P V ----
        #pragma unroll
        for (int ks = 0; ks < 4; ks++) {
            uint32_t bf[8][2];
            #pragma unroll
            for (int nf2 = 0; nf2 < 4; nf2++) {
                int row = nf2 * 16 + brow_lo;
                int seg = (ks * 2 + bseg0) ^ (row & 7);
                uint32_t r0, r1, r2, r3;
                ldsm_x4(r0, r1, r2, r3, vbase + (uint32_t)row * 128 + seg * 16);
                bf[nf2 * 2 + 0][0] = r0; bf[nf2 * 2 + 0][1] = r1;
                bf[nf2 * 2 + 1][0] = r2; bf[nf2 * 2 + 1][1] = r3;
            }
            #pragma unroll
            for (int nf = 0; nf < 8; nf++)
                mma_f16(o[nf], pf[ks], bf[nf]);
        }

        CP_WAIT0();
        __syncthreads();
    }

    // ---- finalize: write C directly as fp16 into g_X3 slot 0 ----
    l0 += __shfl_xor_sync(0xffffffffu, l0, 1);
    l0 += __shfl_xor_sync(0xffffffffu, l0, 2);
    l1 += __shfl_xor_sync(0xffffffffu, l1, 1);
    l1 += __shfl_xor_sync(0xffffffffu, l1, 2);
    const float inv0 = 1.f / l0;
    const float inv1 = 1.f / l1;

    const int t0 = qt * 64 + wid * 16 + (lane >> 2);
    const int b = bh >> 4, h = bh & 15;
    const size_t c0i = ((size_t)(b * T_ + t0)) * E_ + h * D_ + (lane & 3) * 2;
    const size_t c1i = c0i + (size_t)8 * E_;
    #pragma unroll
    for (int nf = 0; nf < 8; nf++) {
        *reinterpret_cast<uint32_t*>(g_X3 + c0i + nf * 8) =
            pack_h2(o[nf][0] * inv0, o[nf][1] * inv0);
        *reinterpret_cast<uint32_t*>(g_X3 + c1i + nf * 8) =
            pack_h2(o[nf][2] * inv1, o[nf][3] * inv1);
    }
}

// ---------------- launch ----------------
extern "C" void kernel_launch(void* const* d_in, const int* in_sizes, int n_in,
                              void* d_out, int out_size)
{
    const float* query = (const float*)d_in[0];
    const float* key   = (const float*)d_in[1];
    const float* value = (const float*)d_in[2];
    const float* wq    = (const float*)d_in[3];
    const float* bq    = (const float*)d_in[4];
    const float* wk    = (const float*)d_in[5];
    const float* bk    = (const float*)d_in[6];
    const float* wv    = (const float*)d_in[7];
    const float* bv    = (const float*)d_in[8];
    const float* wo    = (const float*)d_in[9];
    const float* bo    = (const float*)d_in[10];
    float* out = (float*)d_out;

    __half *X3, *W3;
    cudaGetSymbolAddress((void**)&X3, g_X3);
    cudaGetSymbolAddress((void**)&W3, g_W3);

    static bool attr_done = false;
    if (!attr_done) {
        cudaFuncSetAttribute(gemm_qkv, cudaFuncAttributeMaxDynamicSharedMemorySize, GEMM_SMEM);
        cudaFuncSetAttribute(gemm_out, cudaFuncAttributeMaxDynamicSharedMemorySize, GEMM_SMEM);
        cudaFuncSetAttribute(attn_mma, cudaFuncAttributeMaxDynamicSharedMemorySize, ATTN_SMEM);
        attr_done = true;
    }

    const int actn8 = (M_ * E_) / 8;   // 1,048,576
    const int wn8   = (E_ * E_) / 8;   // 131,072

    conv3_kernel<<<dim3(actn8 / 256, 1, 3), 256>>>(query, key, value, X3, actn8);
    conv3_kernel<<<dim3(wn8 / 256, 1, 3), 256>>>(wq, wk, wv, W3, wn8);

    gemm_qkv<<<dim3(E_ / 128, M_ / 128, 3), 256, GEMM_SMEM>>>(bq, bk, bv);

    conv1_kernel<<<wn8 / 256, 256>>>(wo, W3, wn8);   // slot 0, after gemm_qkv read wq

    attn_mma<<<dim3(BH_, T_ / 64), 128, ATTN_SMEM>>>();   // writes C fp16 into X3 slot 0

    gemm_out<<<dim3(E_ / 128, M_ / 128), 256, GEMM_SMEM>>>(bo, out);
}